// round 6
// baseline (speedup 1.0000x reference)
#include <cuda_runtime.h>
#include <cstdint>

#define BB 16
#define NN 3000
#define MM 300
#define KK 4
#define LL 80
#define PCAP 128
#define GCAP 32
#define THRESH 0.6f

__device__ __forceinline__ float neg_inf() { return __int_as_float(0xff800000); }

// ---------------- exact-order IoU helpers (no FMA contraction) -------------
struct BoxA { float x0, y0, x1, y1, area; };

__device__ __forceinline__ BoxA cvt_box(float cx, float cy, float w, float h) {
    BoxA r;
    float hw = __fmul_rn(0.5f, w);
    float hh = __fmul_rn(0.5f, h);
    r.x0 = __fsub_rn(cx, hw);
    r.y0 = __fsub_rn(cy, hh);
    r.x1 = __fadd_rn(cx, hw);
    r.y1 = __fadd_rn(cy, hh);
    r.area = __fmul_rn(__fsub_rn(r.x1, r.x0), __fsub_rn(r.y1, r.y0));
    return r;
}

// a = gt box, b = proposal box (union = area_a + area_b - inter, in that order)
__device__ __forceinline__ float iou_ab(const BoxA& a, const BoxA& b) {
    float ltx = fmaxf(a.x0, b.x0);
    float lty = fmaxf(a.y0, b.y0);
    float rbx = fminf(a.x1, b.x1);
    float rby = fminf(a.y1, b.y1);
    float wx = fmaxf(__fsub_rn(rbx, ltx), 0.0f);
    float wy = fmaxf(__fsub_rn(rby, lty), 0.0f);
    float inter = __fmul_rn(wx, wy);
    float uni = __fsub_rn(__fadd_rn(a.area, b.area), inter);
    return __fdiv_rn(inter, fmaxf(uni, 1e-9f));
}

// total order: (value desc, index asc) — order-independent, tie-safe
__device__ __forceinline__ bool cmpvi(float v, int i, float w, int j) {
    return (v > w) || (v == w && i < j);
}

__device__ __forceinline__ float sel4f(float v0, float v1, float v2, float v3, int i) {
    float r = v3;
    r = (i == 2) ? v2 : r;
    r = (i == 1) ? v1 : r;
    r = (i == 0) ? v0 : r;
    return r;
}
__device__ __forceinline__ int sel4i(int v0, int v1, int v2, int v3, int i) {
    int r = v3;
    r = (i == 2) ? v2 : r;
    r = (i == 1) ? v1 : r;
    r = (i == 0) ? v0 : r;
    return r;
}

// ---------------- smem layout (dynamic, ~70KB) ------------------------------
struct Smem {
    int   pcnt[LL];
    int   gcnt[LL];
    int   pidx[LL * PCAP];
    int   gbi[LL * GCAP];
    float gx0[MM], gy0[MM], gx1[MM], gy1[MM], gar[MM], gmx[MM];
    int   counts[MM];
    float topv[MM * KK];
    int   topi[MM * KK];
};

// ---------------- fused kernel: one block per batch --------------------------
__global__ void __launch_bounds__(1024, 1)
kFused(const float* __restrict__ props,   // (B,N,4) cxcywh
       const int*   __restrict__ pinds,   // (B,N)
       const int*   __restrict__ gtl,     // (B,M)
       const float* __restrict__ gtb,     // (B,M,4) cxcywh
       float* __restrict__ out) {
    extern __shared__ char raw[];
    Smem* s = reinterpret_cast<Smem*>(raw);
    const int b = blockIdx.x;
    const int t = threadIdx.x;
    const float4* pb = reinterpret_cast<const float4*>(props) + (size_t)b * NN;

    // ---- phase 0: zero counters ----
    if (t < LL) { s->pcnt[t] = 0; s->gcnt[t] = 0; }
    if (t < MM) s->counts[t] = 0;
    __syncthreads();

    // ---- phase S: bucket proposals by label; convert + bucket GTs ----
    for (int n = t; n < NN; n += 1024) {
        int lab = pinds[(size_t)b * NN + n];
        if ((unsigned)lab < LL) {
            int slot = atomicAdd(&s->pcnt[lab], 1);
            if (slot < PCAP) s->pidx[lab * PCAP + slot] = n;
        }
    }
    if (t < MM) {
        int m = t;
        float4 g4 = reinterpret_cast<const float4*>(gtb)[(size_t)b * MM + m];
        BoxA g = cvt_box(g4.x, g4.y, g4.z, g4.w);
        s->gx0[m] = g.x0; s->gy0[m] = g.y0; s->gx1[m] = g.x1; s->gy1[m] = g.y1;
        s->gar[m] = g.area;
        int lab = gtl[(size_t)b * MM + m];
        if ((unsigned)lab < LL) {
            int slot = atomicAdd(&s->gcnt[lab], 1);
            if (slot < GCAP) s->gbi[lab * GCAP + slot] = m;
        }
    }
    __syncthreads();

    // ---- phase A: 8 lanes per GT row -> gmax + stable top-4 ----
    {
        const int warp = t >> 5, lane = t & 31, sub = lane >> 3, lane8 = lane & 7;
#pragma unroll 1
        for (int pass = 0; pass < (MM + 127) / 128; pass++) {
            const int m = pass * 128 + warp * 4 + sub;

            float tv0 = neg_inf(), tv1 = neg_inf(), tv2 = neg_inf(), tv3 = neg_inf();
            int   ti0 = 0x7fffffff, ti1 = 0x7fffffff, ti2 = 0x7fffffff, ti3 = 0x7fffffff;

            int c = 0, base = 0;
            BoxA g;
            if (m < MM) {
                g.x0 = s->gx0[m]; g.y0 = s->gy0[m]; g.x1 = s->gx1[m]; g.y1 = s->gy1[m];
                g.area = s->gar[m];
                int lab = gtl[(size_t)b * MM + m];
                if ((unsigned)lab < LL) {
                    c = min(s->pcnt[lab], PCAP);
                    base = lab * PCAP;
                }
            }

            for (int j = lane8; j < c; j += 8) {
                int n = s->pidx[base + j];
                float4 p4 = pb[n];
                BoxA p = cvt_box(p4.x, p4.y, p4.z, p4.w);
                float v = iou_ab(g, p);
                if (cmpvi(v, n, tv3, ti3)) {
                    if (cmpvi(v, n, tv0, ti0)) {
                        tv3 = tv2; ti3 = ti2; tv2 = tv1; ti2 = ti1; tv1 = tv0; ti1 = ti0;
                        tv0 = v; ti0 = n;
                    } else if (cmpvi(v, n, tv1, ti1)) {
                        tv3 = tv2; ti3 = ti2; tv2 = tv1; ti2 = ti1;
                        tv1 = v; ti1 = n;
                    } else if (cmpvi(v, n, tv2, ti2)) {
                        tv3 = tv2; ti3 = ti2;
                        tv2 = v; ti2 = n;
                    } else {
                        tv3 = v; ti3 = n;
                    }
                }
            }

            // butterfly merge within each 8-lane group (offsets < 8 stay in-group)
#pragma unroll
            for (int off = 4; off > 0; off >>= 1) {
                float bv0 = __shfl_xor_sync(0xffffffffu, tv0, off);
                float bv1 = __shfl_xor_sync(0xffffffffu, tv1, off);
                float bv2 = __shfl_xor_sync(0xffffffffu, tv2, off);
                float bv3 = __shfl_xor_sync(0xffffffffu, tv3, off);
                int   bi0 = __shfl_xor_sync(0xffffffffu, ti0, off);
                int   bi1 = __shfl_xor_sync(0xffffffffu, ti1, off);
                int   bi2 = __shfl_xor_sync(0xffffffffu, ti2, off);
                int   bi3 = __shfl_xor_sync(0xffffffffu, ti3, off);
                float cv[4]; int ci[4];
                int ia = 0, ib = 0;
#pragma unroll
                for (int j = 0; j < 4; j++) {
                    float A  = sel4f(tv0, tv1, tv2, tv3, ia);
                    int   Ai = sel4i(ti0, ti1, ti2, ti3, ia);
                    float Bv = sel4f(bv0, bv1, bv2, bv3, ib);
                    int   Bi = sel4i(bi0, bi1, bi2, bi3, ib);
                    bool ta = cmpvi(A, Ai, Bv, Bi);
                    cv[j] = ta ? A : Bv;
                    ci[j] = ta ? Ai : Bi;
                    ia += ta ? 1 : 0;
                    ib += ta ? 0 : 1;
                }
                tv0 = cv[0]; tv1 = cv[1]; tv2 = cv[2]; tv3 = cv[3];
                ti0 = ci[0]; ti1 = ci[1]; ti2 = ci[2]; ti3 = ci[3];
            }

            if (m < MM && lane8 == 0) {
                s->gmx[m] = tv0;
                s->topv[m * KK + 0] = tv0; s->topv[m * KK + 1] = tv1;
                s->topv[m * KK + 2] = tv2; s->topv[m * KK + 3] = tv3;
                s->topi[m * KK + 0] = ti0; s->topi[m * KK + 1] = ti1;
                s->topi[m * KK + 2] = ti2; s->topi[m * KK + 3] = ti3;
            }
        }
    }
    __syncthreads();

    // ---- phase B: per-proposal argmax over matching GTs -> counts ----
    for (int n = t; n < NN; n += 1024) {
        int lab = pinds[(size_t)b * NN + n];
        if ((unsigned)lab >= LL) continue;
        int c = min(s->gcnt[lab], GCAP);
        if (c == 0) continue;                        // valid_prop false
        float4 p4 = pb[n];
        BoxA p = cvt_box(p4.x, p4.y, p4.z, p4.w);

        float bestv = neg_inf();
        int bestm = 0x7fffffff;
        bool lq = false;
        for (int j = 0; j < c; j++) {
            int m = s->gbi[lab * GCAP + j];
            BoxA g;
            g.x0 = s->gx0[m]; g.y0 = s->gy0[m]; g.x1 = s->gx1[m]; g.y1 = s->gy1[m];
            g.area = s->gar[m];
            float v = iou_ab(g, p);                  // identical bits to phase A
            if (v == s->gmx[m]) lq = true;
            if (v > bestv || (v == bestv && m < bestm)) { bestv = v; bestm = m; }
        }
        // matching IoU >= 0 always beats non-matching NEG -> bestm == ref best_gt
        if (bestv >= THRESH || lq)
            atomicAdd(&s->counts[bestm], 1);
    }
    __syncthreads();

    // ---- phase C: assemble outputs (4 float32 sections) ----
    if (t < MM) {
        const int m = t;
        const int bm = b * MM + m;
        int take = s->counts[m];
        take = take < KK ? take : KK;
        const int S = BB * MM * KK;
#pragma unroll
        for (int j = 0; j < KK; j++) {
            bool val = j < take;
            out[bm * KK + j]         = val ? (float)s->topi[m * KK + j] : -1.0f;
            out[S + bm * KK + j]     = val ? (float)m : -1.0f;
            out[2 * S + bm * KK + j] = val ? 1.0f : 0.0f;
            out[3 * S + bm * KK + j] = val ? s->topv[m * KK + j] : 0.0f;
        }
    }
}

// ---------------- launch ----------------------------------------------------
extern "C" void kernel_launch(void* const* d_in, const int* in_sizes, int n_in,
                              void* d_out, int out_size) {
    // metadata order: pred_logits_match, pred_boxes, init_reference,
    //                 prompt_inds, gt_labels, gt_boxes, max_k
    const float* props = (const float*)d_in[2];   // init_reference (B,N,4)
    const int*   pinds = (const int*)d_in[3];     // prompt_inds    (B,N)
    const int*   gtl   = (const int*)d_in[4];     // gt_labels      (B,M)
    const float* gtb   = (const float*)d_in[5];   // gt_boxes       (B,M,4)

    static bool attr_done = false;
    if (!attr_done) {
        cudaFuncSetAttribute(kFused, cudaFuncAttributeMaxDynamicSharedMemorySize,
                             (int)sizeof(Smem));
        attr_done = true;
    }
    kFused<<<BB, 1024, sizeof(Smem)>>>(props, pinds, gtl, gtb, (float*)d_out);
}

// round 7
// speedup vs baseline: 1.8141x; 1.8141x over previous
#include <cuda_runtime.h>
#include <cstdint>

#define BB 16
#define NN 3000
#define MM 300
#define KK 4
#define LL 80
#define PCAP 128
#define GCAP 32
#define TPB 128
#define THRESH 0.6f

__device__ __forceinline__ float neg_inf() { return __int_as_float(0xff800000); }

// ---------------- exact-order IoU helpers (no FMA contraction) -------------
struct BoxA { float x0, y0, x1, y1, area; };

__device__ __forceinline__ BoxA cvt_box(float cx, float cy, float w, float h) {
    BoxA r;
    float hw = __fmul_rn(0.5f, w);
    float hh = __fmul_rn(0.5f, h);
    r.x0 = __fsub_rn(cx, hw);
    r.y0 = __fsub_rn(cy, hh);
    r.x1 = __fadd_rn(cx, hw);
    r.y1 = __fadd_rn(cy, hh);
    r.area = __fmul_rn(__fsub_rn(r.x1, r.x0), __fsub_rn(r.y1, r.y0));
    return r;
}

// a = gt box, b = proposal box (union = area_a + area_b - inter, in that order)
__device__ __forceinline__ float iou_ab(const BoxA& a, const BoxA& b) {
    float ltx = fmaxf(a.x0, b.x0);
    float lty = fmaxf(a.y0, b.y0);
    float rbx = fminf(a.x1, b.x1);
    float rby = fminf(a.y1, b.y1);
    float wx = fmaxf(__fsub_rn(rbx, ltx), 0.0f);
    float wy = fmaxf(__fsub_rn(rby, lty), 0.0f);
    float inter = __fmul_rn(wx, wy);
    float uni = __fsub_rn(__fadd_rn(a.area, b.area), inter);
    return __fdiv_rn(inter, fmaxf(uni, 1e-9f));
}

// total order: (value desc, index asc) — order-independent, tie-safe
__device__ __forceinline__ bool cmpvi(float v, int i, float w, int j) {
    return (v > w) || (v == w && i < j);
}

__device__ __forceinline__ float sel4f(float v0, float v1, float v2, float v3, int i) {
    float r = v3;
    r = (i == 2) ? v2 : r;
    r = (i == 1) ? v1 : r;
    r = (i == 0) ? v0 : r;
    return r;
}
__device__ __forceinline__ int sel4i(int v0, int v1, int v2, int v3, int i) {
    int r = v3;
    r = (i == 2) ? v2 : r;
    r = (i == 1) ? v1 : r;
    r = (i == 0) ? v0 : r;
    return r;
}

// ---------------- fused kernel: one block per (batch, label) ----------------
__global__ void __launch_bounds__(TPB)
kBucket(const float* __restrict__ props,   // (B,N,4) cxcywh
        const int*   __restrict__ pinds,   // (B,N)
        const int*   __restrict__ gtl,     // (B,M)
        const float* __restrict__ gtb,     // (B,M,4) cxcywh
        float* __restrict__ out) {
    __shared__ float spx0[PCAP], spy0[PCAP], spx1[PCAP], spy1[PCAP], spar[PCAP];
    __shared__ int   spn[PCAP];
    __shared__ float sgx0[GCAP], sgy0[GCAP], sgx1[GCAP], sgy1[GCAP], sgar[GCAP], sgmx[GCAP];
    __shared__ int   sgm[GCAP];
    __shared__ int   scnt[GCAP];
    __shared__ float stv[GCAP * KK];
    __shared__ int   sti[GCAP * KK];
    __shared__ int   spcnt, sgcnt;

    const int b   = blockIdx.x / LL;
    const int lab = blockIdx.x % LL;
    const int t   = threadIdx.x;

    if (t == 0) { spcnt = 0; sgcnt = 0; }
    if (t < GCAP) scnt[t] = 0;
    __syncthreads();

    // ---- build GT bucket (converted boxes) ----
    for (int m = t; m < MM; m += TPB) {
        if (gtl[(size_t)b * MM + m] == lab) {
            int slot = atomicAdd(&sgcnt, 1);
            if (slot < GCAP) {
                float4 g4 = reinterpret_cast<const float4*>(gtb)[(size_t)b * MM + m];
                BoxA g = cvt_box(g4.x, g4.y, g4.z, g4.w);
                sgx0[slot] = g.x0; sgy0[slot] = g.y0; sgx1[slot] = g.x1; sgy1[slot] = g.y1;
                sgar[slot] = g.area;
                sgm[slot]  = m;
            }
        }
    }
    // ---- build proposal bucket (converted boxes) ----
#pragma unroll 4
    for (int n = t; n < NN; n += TPB) {
        if (pinds[(size_t)b * NN + n] == lab) {
            int slot = atomicAdd(&spcnt, 1);
            if (slot < PCAP) {
                float4 p4 = reinterpret_cast<const float4*>(props)[(size_t)b * NN + n];
                BoxA p = cvt_box(p4.x, p4.y, p4.z, p4.w);
                spx0[slot] = p.x0; spy0[slot] = p.y0; spx1[slot] = p.x1; spy1[slot] = p.y1;
                spar[slot] = p.area;
                spn[slot]  = n;
            }
        }
    }
    __syncthreads();

    const int gc = min(sgcnt, GCAP);
    if (gc == 0) return;                         // no output rows owned by this block
    const int pc = min(spcnt, PCAP);

    // ---- phase A: warp per GT slot -> gmax + stable top-4 ----
    {
        const int warp = t >> 5, lane = t & 31;
        for (int j = warp; j < gc; j += TPB / 32) {
            BoxA g;
            g.x0 = sgx0[j]; g.y0 = sgy0[j]; g.x1 = sgx1[j]; g.y1 = sgy1[j]; g.area = sgar[j];

            float tv0 = neg_inf(), tv1 = neg_inf(), tv2 = neg_inf(), tv3 = neg_inf();
            int   ti0 = 0x7fffffff, ti1 = 0x7fffffff, ti2 = 0x7fffffff, ti3 = 0x7fffffff;

            for (int i = lane; i < pc; i += 32) {
                BoxA p;
                p.x0 = spx0[i]; p.y0 = spy0[i]; p.x1 = spx1[i]; p.y1 = spy1[i]; p.area = spar[i];
                int n = spn[i];
                float v = iou_ab(g, p);
                if (cmpvi(v, n, tv3, ti3)) {
                    if (cmpvi(v, n, tv0, ti0)) {
                        tv3 = tv2; ti3 = ti2; tv2 = tv1; ti2 = ti1; tv1 = tv0; ti1 = ti0;
                        tv0 = v; ti0 = n;
                    } else if (cmpvi(v, n, tv1, ti1)) {
                        tv3 = tv2; ti3 = ti2; tv2 = tv1; ti2 = ti1;
                        tv1 = v; ti1 = n;
                    } else if (cmpvi(v, n, tv2, ti2)) {
                        tv3 = tv2; ti3 = ti2;
                        tv2 = v; ti2 = n;
                    } else {
                        tv3 = v; ti3 = n;
                    }
                }
            }

            // warp butterfly merge of sorted-4 lists (total order -> all lanes agree)
#pragma unroll
            for (int off = 16; off > 0; off >>= 1) {
                float bv0 = __shfl_xor_sync(0xffffffffu, tv0, off);
                float bv1 = __shfl_xor_sync(0xffffffffu, tv1, off);
                float bv2 = __shfl_xor_sync(0xffffffffu, tv2, off);
                float bv3 = __shfl_xor_sync(0xffffffffu, tv3, off);
                int   bi0 = __shfl_xor_sync(0xffffffffu, ti0, off);
                int   bi1 = __shfl_xor_sync(0xffffffffu, ti1, off);
                int   bi2 = __shfl_xor_sync(0xffffffffu, ti2, off);
                int   bi3 = __shfl_xor_sync(0xffffffffu, ti3, off);
                float cv[4]; int ci[4];
                int ia = 0, ib = 0;
#pragma unroll
                for (int q = 0; q < 4; q++) {
                    float A  = sel4f(tv0, tv1, tv2, tv3, ia);
                    int   Ai = sel4i(ti0, ti1, ti2, ti3, ia);
                    float Bv = sel4f(bv0, bv1, bv2, bv3, ib);
                    int   Bi = sel4i(bi0, bi1, bi2, bi3, ib);
                    bool ta = cmpvi(A, Ai, Bv, Bi);
                    cv[q] = ta ? A : Bv;
                    ci[q] = ta ? Ai : Bi;
                    ia += ta ? 1 : 0;
                    ib += ta ? 0 : 1;
                }
                tv0 = cv[0]; tv1 = cv[1]; tv2 = cv[2]; tv3 = cv[3];
                ti0 = ci[0]; ti1 = ci[1]; ti2 = ci[2]; ti3 = ci[3];
            }

            if (lane == 0) {
                sgmx[j] = tv0;
                stv[j * KK + 0] = tv0; stv[j * KK + 1] = tv1;
                stv[j * KK + 2] = tv2; stv[j * KK + 3] = tv3;
                sti[j * KK + 0] = ti0; sti[j * KK + 1] = ti1;
                sti[j * KK + 2] = ti2; sti[j * KK + 3] = ti3;
            }
        }
    }
    __syncthreads();

    // ---- phase B: thread per proposal -> argmax over bucket GTs -> counts ----
    for (int i = t; i < pc; i += TPB) {
        BoxA p;
        p.x0 = spx0[i]; p.y0 = spy0[i]; p.x1 = spx1[i]; p.y1 = spy1[i]; p.area = spar[i];

        float bestv = neg_inf();
        int bestm = 0x7fffffff, bestj = 0;
        bool lq = false;
        for (int j = 0; j < gc; j++) {
            BoxA g;
            g.x0 = sgx0[j]; g.y0 = sgy0[j]; g.x1 = sgx1[j]; g.y1 = sgy1[j]; g.area = sgar[j];
            float v = iou_ab(g, p);                 // identical bits to phase A
            if (v == sgmx[j]) lq = true;
            int m = sgm[j];
            if (v > bestv || (v == bestv && m < bestm)) { bestv = v; bestm = m; bestj = j; }
        }
        // matching IoU >= 0 beats all non-matching NEG entries -> bestm == ref best_gt
        if (bestv >= THRESH || lq)
            atomicAdd(&scnt[bestj], 1);
    }
    __syncthreads();

    // ---- phase C: write output rows owned by this block ----
    for (int j = t; j < gc; j += TPB) {
        const int m = sgm[j];
        const int bm = b * MM + m;
        int take = scnt[j];
        take = take < KK ? take : KK;
        const int S = BB * MM * KK;
#pragma unroll
        for (int q = 0; q < KK; q++) {
            bool val = q < take;
            out[bm * KK + q]         = val ? (float)sti[j * KK + q] : -1.0f;
            out[S + bm * KK + q]     = val ? (float)m : -1.0f;
            out[2 * S + bm * KK + q] = val ? 1.0f : 0.0f;
            out[3 * S + bm * KK + q] = val ? stv[j * KK + q] : 0.0f;
        }
    }
}

// ---------------- launch ----------------------------------------------------
extern "C" void kernel_launch(void* const* d_in, const int* in_sizes, int n_in,
                              void* d_out, int out_size) {
    // metadata order: pred_logits_match, pred_boxes, init_reference,
    //                 prompt_inds, gt_labels, gt_boxes, max_k
    const float* props = (const float*)d_in[2];   // init_reference (B,N,4)
    const int*   pinds = (const int*)d_in[3];     // prompt_inds    (B,N)
    const int*   gtl   = (const int*)d_in[4];     // gt_labels      (B,M)
    const float* gtb   = (const float*)d_in[5];   // gt_boxes       (B,M,4)

    kBucket<<<BB * LL, TPB>>>(props, pinds, gtl, gtb, (float*)d_out);
}